// round 13
// baseline (speedup 1.0000x reference)
#include <cuda_runtime.h>
#include <cuda_fp8.h>
#include <math.h>
#include <stdint.h>

#define NSB    2050          // real sequence (S = L + w - 1)
#define NP     2176          // padded storage stride (17 * 128)
#define NMAIN  2048          // main GEMM extent (16 tiles of 128)
#define LOUT   2048
#define HD     128
#define NBATCH 32
#define BM     128
#define BN     128
#define POISON 3e18f
#define TILE_BYTES 16384     // 128 rows x 128 B e4m3 (contiguous, pre-swizzled)
#define SM_TOTAL   (1024 + 2 * TILE_BYTES)

// Scratch (__device__ globals: allocation-free rule).
// e4m3 rows PRE-SWIZZLED: 16B granule g of row r lives at granule (g ^ (r & 7)).
__device__ __align__(16) uint8_t g_x0q[NBATCH * NP * HD];
__device__ __align__(16) uint8_t g_x1q[NBATCH * NP * HD];
__device__ float g_sq0[NBATCH * NP];
__device__ float g_sq1[NBATCH * NP];
__device__ float g_r[NBATCH * NP];
__device__ float g_c[NBATCH * NP];

__device__ __forceinline__ uint32_t smem_u32(const void* p) {
    uint32_t a;
    asm("{ .reg .u64 t; cvta.to.shared.u64 t, %1; cvt.u32.u64 %0, t; }"
        : "=r"(a) : "l"(p));
    return a;
}
__device__ __forceinline__ void ldsm_x4(uint32_t a, uint32_t& r0, uint32_t& r1,
                                        uint32_t& r2, uint32_t& r3) {
    asm volatile("ldmatrix.sync.aligned.m8n8.x4.shared.b16 {%0,%1,%2,%3}, [%4];"
                 : "=r"(r0), "=r"(r1), "=r"(r2), "=r"(r3) : "r"(a));
}
#define MBAR_INIT(a, c) \
    asm volatile("mbarrier.init.shared.b64 [%0], %1;" :: "r"(a), "r"((uint32_t)(c)) : "memory")
#define MBAR_EXPECT_TX(a, n) \
    asm volatile("mbarrier.arrive.expect_tx.shared.b64 _, [%0], %1;" \
                 :: "r"(a), "r"((uint32_t)(n)) : "memory")
#define BULK_G2S(dst, src, n, mbar) \
    asm volatile("cp.async.bulk.shared::cluster.global.mbarrier::complete_tx::bytes " \
                 "[%0], [%1], %2, [%3];" \
                 :: "r"(dst), "l"(src), "r"((uint32_t)(n)), "r"(mbar) : "memory")
#define MBAR_WAIT(addr, par) do {                                              \
    uint32_t _m = (addr), _p = (par), _d;                                      \
    asm volatile("{ .reg .pred p; mbarrier.try_wait.parity.acquire.cta.shared::cta.b64 p, [%1], %2; selp.b32 %0,1,0,p; }" \
                 : "=r"(_d) : "r"(_m), "r"(_p) : "memory");                    \
    if (!_d) {                                                                 \
        asm volatile("{ .reg .pred P1; WL%=: mbarrier.try_wait.parity.acquire.cta.shared::cta.b64 P1, [%0], %1, 0x989680; @P1 bra.uni WD%=; bra.uni WL%=; WD%=: }" \
                     :: "r"(_m), "r"(_p) : "memory");                          \
    } } while (0)

// ---------------------------------------------------------------------------
// Kernel 1: warp-per-row squared norms (exact fp32) + e4m3 quantization,
// SWIZZLED output (verified R11).
// ---------------------------------------------------------------------------
__global__ void prep_kernel(const float* __restrict__ x0,
                            const float* __restrict__ x1) {
    int gw   = (blockIdx.x * blockDim.x + threadIdx.x) >> 5;
    int lane = threadIdx.x & 31;
    if (gw >= NBATCH * NP) return;
    int b = gw / NP;
    int s = gw - b * NP;
    if (lane == 0) { g_r[gw] = 0.f; g_c[gw] = 0.f; }

    uint32_t boff = (uint32_t)((((lane >> 2) ^ (s & 7)) << 4) + (lane & 3) * 4);
    char* r0 = (char*)(g_x0q + (size_t)gw * HD) + boff;
    char* r1 = (char*)(g_x1q + (size_t)gw * HD) + boff;

    if (s < NSB) {
        float4 v0 = ((const float4*)(x0 + ((size_t)b * NSB + s) * HD))[lane];
        float4 v1 = ((const float4*)(x1 + ((size_t)b * NSB + s) * HD))[lane];
        uint32_t w0 =
            (uint32_t)__nv_cvt_float2_to_fp8x2(make_float2(v0.x, v0.y),
                                               __NV_SATFINITE, __NV_E4M3) |
            ((uint32_t)__nv_cvt_float2_to_fp8x2(make_float2(v0.z, v0.w),
                                                __NV_SATFINITE, __NV_E4M3) << 16);
        uint32_t w1 =
            (uint32_t)__nv_cvt_float2_to_fp8x2(make_float2(v1.x, v1.y),
                                               __NV_SATFINITE, __NV_E4M3) |
            ((uint32_t)__nv_cvt_float2_to_fp8x2(make_float2(v1.z, v1.w),
                                                __NV_SATFINITE, __NV_E4M3) << 16);
        *(uint32_t*)r0 = w0;
        *(uint32_t*)r1 = w1;
        float p = v0.x * v0.x + v0.y * v0.y + v0.z * v0.z + v0.w * v0.w;
        float q = v1.x * v1.x + v1.y * v1.y + v1.z * v1.z + v1.w * v1.w;
#pragma unroll
        for (int d = 16; d >= 1; d >>= 1) {
            p += __shfl_xor_sync(0xffffffffu, p, d);
            q += __shfl_xor_sync(0xffffffffu, q, d);
        }
        if (lane == 0) { g_sq0[gw] = p; g_sq1[gw] = q; }
    } else {
        *(uint32_t*)r0 = 0u;
        *(uint32_t*)r1 = 0u;
        if (lane == 0) { g_sq0[gw] = POISON; g_sq1[gw] = POISON; }
    }
}

// ---------------------------------------------------------------------------
// Kernel 2: e4m3 m16n8k32 distance GEMM, THREE CTAs/SM, TWO N-passes per
// tile to fit the 85-reg budget (acc = 32 f32 per pass). Bulk-DMA loads,
// XOR-swizzled ldmatrix, fused epilogue + staged reduction.
// ---------------------------------------------------------------------------
__global__ __launch_bounds__(256, 3)
void dist_kernel() {
    extern __shared__ __align__(1024) char smem[];
    __shared__ float s_c[BM];
    __shared__ float s_r[BN];

    const int b  = blockIdx.z;
    const int i0 = blockIdx.y * BM;
    const int j0 = blockIdx.x * BN;
    const int tid  = threadIdx.x;
    const int wid  = tid >> 5;
    const int lane = tid & 31;
    const int g  = lane >> 2;
    const int tg = lane & 3;
    const int wm = (wid & 3) * 32;
    const int wn = (wid >> 2) * 64;

    const uint32_t sbar = smem_u32(smem);
    const uint32_t sA = sbar + 1024;
    const uint32_t sB = sA + TILE_BYTES;

    if (tid == 0) MBAR_INIT(sbar, 1);
    __syncthreads();
    if (tid == 0) {
        MBAR_EXPECT_TX(sbar, 2 * TILE_BYTES);
        BULK_G2S(sA, (const char*)(g_x0q + ((size_t)b * NP + i0) * HD),
                 TILE_BYTES, sbar);
        BULK_G2S(sB, (const char*)(g_x1q + ((size_t)b * NP + j0) * HD),
                 TILE_BYTES, sbar);
    }

    const size_t bNP = (size_t)b * NP;
    float sqi[4];
#pragma unroll
    for (int mi = 0; mi < 2; mi++)
#pragma unroll
        for (int h = 0; h < 2; h++)
            sqi[mi * 2 + h] = g_sq0[bNP + i0 + wm + mi * 16 + h * 8 + g];

    if (tid < BM) s_c[tid] = 0.f;
    else          s_r[tid - BM] = 0.f;

    // ldmatrix geometry (rows are 128 B; swizzle: granule ^= row & 7)
    const int l7  = lane & 7;
    const int hiA = (lane >> 4) & 1;
    const int hiB = (lane >> 3) & 1;
    const uint32_t baseA = sA + (uint32_t)((wm + (lane & 7) + ((lane >> 3) & 1) * 8) << 7);
    const uint32_t baseB = sB + (uint32_t)((wn + (lane & 7) + ((lane >> 4) & 1) * 8) << 7);

    MBAR_WAIT(sbar, 0);

    float rs[4] = {0.f, 0.f, 0.f, 0.f};   // row sums carried across both passes

#pragma unroll
    for (int p = 0; p < 2; p++) {          // N-pass: cols [p*32, p*32+32) of warp tile
        float acc[2][4][4];
#pragma unroll
        for (int mi = 0; mi < 2; mi++)
#pragma unroll
            for (int ni = 0; ni < 4; ni++)
#pragma unroll
                for (int c = 0; c < 4; c++) acc[mi][ni][c] = 0.f;

#pragma unroll
        for (int ks = 0; ks < 4; ks++) {   // K chunks of 32 e4m3
            const uint32_t offA = (uint32_t)(((2 * ks + hiA) ^ l7) << 4);
            const uint32_t offB = (uint32_t)(((2 * ks + hiB) ^ l7) << 4);
            uint32_t a[2][4], bb[4][2];
#pragma unroll
            for (int mi = 0; mi < 2; mi++)
                ldsm_x4(baseA + mi * 2048 + offA,
                        a[mi][0], a[mi][1], a[mi][2], a[mi][3]);
#pragma unroll
            for (int np = 0; np < 2; np++)
                ldsm_x4(baseB + p * 4096 + np * 2048 + offB,
                        bb[np * 2][0], bb[np * 2][1],
                        bb[np * 2 + 1][0], bb[np * 2 + 1][1]);
#pragma unroll
            for (int mi = 0; mi < 2; mi++)
#pragma unroll
                for (int ni = 0; ni < 4; ni++) {
                    float* c = acc[mi][ni];
                    asm volatile(
                        "mma.sync.aligned.m16n8k32.row.col.f32.e4m3.e4m3.f32 "
                        "{%0,%1,%2,%3}, {%4,%5,%6,%7}, {%8,%9}, {%0,%1,%2,%3};"
                        : "+f"(c[0]), "+f"(c[1]), "+f"(c[2]), "+f"(c[3])
                        : "r"(a[mi][0]), "r"(a[mi][1]), "r"(a[mi][2]), "r"(a[mi][3]),
                          "r"(bb[ni][0]), "r"(bb[ni][1]));
                }
        }

        // per-pass epilogue
        float sqj[8];
#pragma unroll
        for (int ni = 0; ni < 4; ni++)
#pragma unroll
            for (int e = 0; e < 2; e++)
                sqj[ni * 2 + e] = g_sq1[bNP + j0 + wn + p * 32 + ni * 8 + 2 * tg + e];

        float cs[8];
#pragma unroll
        for (int i = 0; i < 8; i++) cs[i] = 0.f;

#pragma unroll
        for (int mi = 0; mi < 2; mi++)
#pragma unroll
            for (int ni = 0; ni < 4; ni++)
#pragma unroll
                for (int c = 0; c < 4; c++) {
                    int h = c >> 1, e = c & 1;
                    float d2 = fmaxf(fmaf(acc[mi][ni][c], -2.f,
                                          sqi[mi * 2 + h] + sqj[ni * 2 + e]), 0.f);
                    float Aij;
                    if (d2 < 64.f) {
                        Aij = 1.f / (1.f + sqrtf(d2));
                    } else {
                        float u;
                        asm("rsqrt.approx.f32 %0, %1;" : "=f"(u) : "f"(d2));
                        float t = fmaf(-u, 1.f - u, 1.f);
                        Aij = u * fmaf(-u, t, 1.f);
                    }
                    rs[mi * 2 + h] += Aij;
                    cs[ni * 2 + e] += Aij;
                }

        // col sums of this pass: reduce across g, stage to s_r
#pragma unroll
        for (int i = 0; i < 8; i++) {
            cs[i] += __shfl_xor_sync(0xffffffffu, cs[i], 4);
            cs[i] += __shfl_xor_sync(0xffffffffu, cs[i], 8);
            cs[i] += __shfl_xor_sync(0xffffffffu, cs[i], 16);
        }
        if (g == 0) {
#pragma unroll
            for (int ni = 0; ni < 4; ni++)
#pragma unroll
                for (int e = 0; e < 2; e++)
                    atomicAdd(&s_r[wn + p * 32 + ni * 8 + 2 * tg + e],
                              cs[ni * 2 + e]);
        }
    }

    // row sums: reduce across tg, stage to s_c
#pragma unroll
    for (int i = 0; i < 4; i++) {
        rs[i] += __shfl_xor_sync(0xffffffffu, rs[i], 1);
        rs[i] += __shfl_xor_sync(0xffffffffu, rs[i], 2);
    }
    if (tg == 0) {
#pragma unroll
        for (int mi = 0; mi < 2; mi++)
#pragma unroll
            for (int h = 0; h < 2; h++)
                atomicAdd(&s_c[wm + mi * 16 + h * 8 + g], rs[mi * 2 + h]);
    }
    __syncthreads();

    if (tid < BM) atomicAdd(&g_c[bNP + i0 + tid], s_c[tid]);
    else          atomicAdd(&g_r[bNP + j0 + (tid - BM)], s_r[tid - BM]);
}

// ---------------------------------------------------------------------------
// Kernel 2b: edge strips (exact fp32 dots), unchanged (verified R10).
// ---------------------------------------------------------------------------
__global__ void edge_kernel(const float* __restrict__ x0,
                            const float* __restrict__ x1) {
    const int mode = blockIdx.y;                 // 0 = E1, 1 = E2
    int gw   = (blockIdx.x * blockDim.x + threadIdx.x) >> 5;
    int lane = threadIdx.x & 31;
    const int nch = (mode == 0) ? 65 : 64;
    int b  = gw / nch;
    int ch = gw - b * nch;
    if (b >= NBATCH) return;

    int t = ch * 32 + lane;
    bool valid = (mode == 0) ? (t < NSB) : (t < NMAIN);
    int tc = valid ? t : 0;

    const float* longRow;
    const float* e0;
    const float* e1;
    if (mode == 0) {
        longRow = x1 + ((size_t)b * NSB + tc) * HD;
        e0 = x0 + ((size_t)b * NSB + 2048) * HD;
        e1 = x0 + ((size_t)b * NSB + 2049) * HD;
    } else {
        longRow = x0 + ((size_t)b * NSB + tc) * HD;
        e0 = x1 + ((size_t)b * NSB + 2048) * HD;
        e1 = x1 + ((size_t)b * NSB + 2049) * HD;
    }

    float d0 = 0.f, d1 = 0.f;
#pragma unroll
    for (int k4 = 0; k4 < HD / 4; k4++) {
        float4 bv = ((const float4*)longRow)[k4];
        float4 a0 = __ldg(&((const float4*)e0)[k4]);
        float4 a1 = __ldg(&((const float4*)e1)[k4]);
        d0 = fmaf(a0.x, bv.x, fmaf(a0.y, bv.y, fmaf(a0.z, bv.z, fmaf(a0.w, bv.w, d0))));
        d1 = fmaf(a1.x, bv.x, fmaf(a1.y, bv.y, fmaf(a1.z, bv.z, fmaf(a1.w, bv.w, d1))));
    }

    const size_t bNP = (size_t)b * NP;
    float sqt, sqe0, sqe1;
    if (mode == 0) {
        sqt  = g_sq1[bNP + tc];
        sqe0 = g_sq0[bNP + 2048];
        sqe1 = g_sq0[bNP + 2049];
    } else {
        sqt  = g_sq0[bNP + tc];
        sqe0 = g_sq1[bNP + 2048];
        sqe1 = g_sq1[bNP + 2049];
    }

    float A0 = 0.f, A1 = 0.f;
    if (valid) {
        float q0 = fmaxf(sqe0 + sqt - 2.f * d0, 0.f);
        float q1 = fmaxf(sqe1 + sqt - 2.f * d1, 0.f);
        A0 = 1.f / (1.f + sqrtf(q0));
        A1 = 1.f / (1.f + sqrtf(q1));
        if (mode == 0) {
            atomicAdd(&g_r[bNP + t], A0 + A1);
        } else {
            atomicAdd(&g_c[bNP + t], A0 + A1);
        }
    }
#pragma unroll
    for (int d = 16; d >= 1; d >>= 1) {
        A0 += __shfl_xor_sync(0xffffffffu, A0, d);
        A1 += __shfl_xor_sync(0xffffffffu, A1, d);
    }
    if (lane == 0) {
        if (mode == 0) {
            atomicAdd(&g_c[bNP + 2048], A0);
            atomicAdd(&g_c[bNP + 2049], A1);
        } else {
            atomicAdd(&g_r[bNP + 2048], A0);
            atomicAdd(&g_r[bNP + 2049], A1);
        }
    }
}

// ---------------------------------------------------------------------------
// Kernel 3: windowed weighted pooling; 2 outputs per thread (row reuse).
// ---------------------------------------------------------------------------
__global__ void window_kernel(const float* __restrict__ x0,
                              const float* __restrict__ x1,
                              float* __restrict__ out) {
    int t = blockIdx.x * blockDim.x + threadIdx.x;
    const int H4 = HD / 4;
    if (t >= NBATCH * (LOUT / 2) * H4) return;
    int h4 = t & 31;
    int lp = (t >> 5) & (LOUT / 2 - 1);
    int b  = t >> 15;
    int l0 = lp * 2;

    const float4* x04 = (const float4*)x0;
    const float4* x14 = (const float4*)x1;
    size_t base = ((size_t)b * NSB + l0) * H4 + h4;

    float rw[4], cw[4];
    float4 v0[4], v1[4];
#pragma unroll
    for (int s = 0; s < 4; s++) {
        rw[s] = g_r[(size_t)b * NP + l0 + s];
        cw[s] = g_c[(size_t)b * NP + l0 + s];
        v0[s] = x04[base + (size_t)s * H4];
        v1[s] = x14[base + (size_t)s * H4];
    }

    float4* o = (float4*)out;
    size_t obase = ((size_t)b * LOUT + l0) * H4 + h4;
    const size_t O1 = (size_t)NBATCH * LOUT * H4;
#pragma unroll
    for (int q = 0; q < 2; q++) {
        float4 a0, a1;
        a0.x = rw[q] * v0[q].x; a0.y = rw[q] * v0[q].y;
        a0.z = rw[q] * v0[q].z; a0.w = rw[q] * v0[q].w;
        a1.x = cw[q] * v1[q].x; a1.y = cw[q] * v1[q].y;
        a1.z = cw[q] * v1[q].z; a1.w = cw[q] * v1[q].w;
#pragma unroll
        for (int s = 1; s < 3; s++) {
            a0.x += rw[q + s] * v0[q + s].x; a0.y += rw[q + s] * v0[q + s].y;
            a0.z += rw[q + s] * v0[q + s].z; a0.w += rw[q + s] * v0[q + s].w;
            a1.x += cw[q + s] * v1[q + s].x; a1.y += cw[q + s] * v1[q + s].y;
            a1.z += cw[q + s] * v1[q + s].z; a1.w += cw[q + s] * v1[q + s].w;
        }
        o[obase + (size_t)q * H4] = a0;
        o[O1 + obase + (size_t)q * H4] = a1;
    }
}

// ---------------------------------------------------------------------------
extern "C" void kernel_launch(void* const* d_in, const int* in_sizes, int n_in,
                              void* d_out, int out_size) {
    const float* x0 = (const float*)d_in[0];
    const float* x1 = (const float*)d_in[1];
    float* out = (float*)d_out;

    cudaFuncSetAttribute(dist_kernel,
                         cudaFuncAttributeMaxDynamicSharedMemorySize, SM_TOTAL);

    prep_kernel<<<(NBATCH * NP * 32 + 255) / 256, 256>>>(x0, x1);

    dim3 grid(NMAIN / BN, NMAIN / BM, NBATCH);   // 16 x 16 x 32
    dist_kernel<<<grid, 256, SM_TOTAL>>>();

    dim3 egrid((NBATCH * 65 * 32 + 255) / 256, 2, 1);
    edge_kernel<<<egrid, 256>>>(x0, x1);

    window_kernel<<<(NBATCH * (LOUT / 2) * (HD / 4) + 255) / 256, 256>>>(x0, x1, out);
}

// round 14
// speedup vs baseline: 1.2622x; 1.2622x over previous
#include <cuda_runtime.h>
#include <cuda_fp16.h>
#include <math.h>
#include <stdint.h>

#define NSB    2050          // real sequence (S = L + w - 1)
#define NP     2176          // padded storage stride (17 * 128)
#define NMAIN  2048          // main GEMM extent
#define LOUT   2048
#define HD     128
#define NBATCH 32
#define BM     128
#define BN     64
#define POISON 3e18f
#define TILE_A 32768         // 128 rows x 256 B fp16 (contiguous, pre-swizzled)
#define TILE_B 16384         // 64 rows x 256 B fp16
#define SM_TOTAL (1024 + TILE_A + TILE_B)

// Scratch (__device__ globals: allocation-free rule).
// fp16 rows PRE-SWIZZLED: 16B granule g of row r lives at granule (g ^ (r & 7)).
__device__ __align__(16) __half g_x0h[NBATCH * NP * HD];
__device__ __align__(16) __half g_x1h[NBATCH * NP * HD];
__device__ float g_sq0[NBATCH * NP];
__device__ float g_sq1[NBATCH * NP];
__device__ float g_r[NBATCH * NP];
__device__ float g_c[NBATCH * NP];

__device__ __forceinline__ uint32_t smem_u32(const void* p) {
    uint32_t a;
    asm("{ .reg .u64 t; cvta.to.shared.u64 t, %1; cvt.u32.u64 %0, t; }"
        : "=r"(a) : "l"(p));
    return a;
}
__device__ __forceinline__ void ldsm_x4(uint32_t a, uint32_t& r0, uint32_t& r1,
                                        uint32_t& r2, uint32_t& r3) {
    asm volatile("ldmatrix.sync.aligned.m8n8.x4.shared.b16 {%0,%1,%2,%3}, [%4];"
                 : "=r"(r0), "=r"(r1), "=r"(r2), "=r"(r3) : "r"(a));
}
#define MBAR_INIT(a, c) \
    asm volatile("mbarrier.init.shared.b64 [%0], %1;" :: "r"(a), "r"((uint32_t)(c)) : "memory")
#define MBAR_EXPECT_TX(a, n) \
    asm volatile("mbarrier.arrive.expect_tx.shared.b64 _, [%0], %1;" \
                 :: "r"(a), "r"((uint32_t)(n)) : "memory")
#define BULK_G2S(dst, src, n, mbar) \
    asm volatile("cp.async.bulk.shared::cluster.global.mbarrier::complete_tx::bytes " \
                 "[%0], [%1], %2, [%3];" \
                 :: "r"(dst), "l"(src), "r"((uint32_t)(n)), "r"(mbar) : "memory")
#define MBAR_WAIT(addr, par) do {                                              \
    uint32_t _m = (addr), _p = (par), _d;                                      \
    asm volatile("{ .reg .pred p; mbarrier.try_wait.parity.acquire.cta.shared::cta.b64 p, [%1], %2; selp.b32 %0,1,0,p; }" \
                 : "=r"(_d) : "r"(_m), "r"(_p) : "memory");                    \
    if (!_d) {                                                                 \
        asm volatile("{ .reg .pred P1; WL%=: mbarrier.try_wait.parity.acquire.cta.shared::cta.b64 P1, [%0], %1, 0x989680; @P1 bra.uni WD%=; bra.uni WL%=; WD%=: }" \
                     :: "r"(_m), "r"(_p) : "memory");                          \
    } } while (0)

// ---------------------------------------------------------------------------
// Kernel 1: warp-per-row squared norms + fp16 conversion, SWIZZLED output.
// ---------------------------------------------------------------------------
__global__ void prep_kernel(const float* __restrict__ x0,
                            const float* __restrict__ x1) {
    int gw   = (blockIdx.x * blockDim.x + threadIdx.x) >> 5;
    int lane = threadIdx.x & 31;
    if (gw >= NBATCH * NP) return;
    int b = gw / NP;
    int s = gw - b * NP;
    if (lane == 0) { g_r[gw] = 0.f; g_c[gw] = 0.f; }

    uint32_t boff = (uint32_t)((((lane >> 1) ^ (s & 7)) << 4) + (lane & 1) * 8);
    char* r0 = (char*)(g_x0h + (size_t)gw * HD) + boff;
    char* r1 = (char*)(g_x1h + (size_t)gw * HD) + boff;

    if (s < NSB) {
        float4 v0 = ((const float4*)(x0 + ((size_t)b * NSB + s) * HD))[lane];
        float4 v1 = ((const float4*)(x1 + ((size_t)b * NSB + s) * HD))[lane];
        __half2 p0 = __float22half2_rn(make_float2(v0.x, v0.y));
        __half2 p1 = __float22half2_rn(make_float2(v0.z, v0.w));
        __half2 q0 = __float22half2_rn(make_float2(v1.x, v1.y));
        __half2 q1 = __float22half2_rn(make_float2(v1.z, v1.w));
        uint2 w0, w1;
        w0.x = *(uint32_t*)&p0; w0.y = *(uint32_t*)&p1;
        w1.x = *(uint32_t*)&q0; w1.y = *(uint32_t*)&q1;
        *(uint2*)r0 = w0; *(uint2*)r1 = w1;
        float p = v0.x * v0.x + v0.y * v0.y + v0.z * v0.z + v0.w * v0.w;
        float q = v1.x * v1.x + v1.y * v1.y + v1.z * v1.z + v1.w * v1.w;
#pragma unroll
        for (int d = 16; d >= 1; d >>= 1) {
            p += __shfl_xor_sync(0xffffffffu, p, d);
            q += __shfl_xor_sync(0xffffffffu, q, d);
        }
        if (lane == 0) { g_sq0[gw] = p; g_sq1[gw] = q; }
    } else {
        uint2 z = make_uint2(0u, 0u);
        *(uint2*)r0 = z; *(uint2*)r1 = z;
        if (lane == 0) { g_sq0[gw] = POISON; g_sq1[gw] = POISON; }
    }
}

// ---------------------------------------------------------------------------
// Kernel 2: fp16 mma.sync (f16 acc) distance GEMM, 128x64 tiles,
// FOUR CTAs per SM for deeper tensor-pipe phase overlap. Bulk-DMA loads,
// XOR-swizzled ldmatrix, fused A = 1/(1+dist) epilogue + reduction.
// ---------------------------------------------------------------------------
__global__ __launch_bounds__(256, 4)
void dist_kernel() {
    extern __shared__ __align__(1024) char smem[];
    __shared__ float s_c[BM];
    __shared__ float s_r[BN];

    const int b  = blockIdx.z;
    const int i0 = blockIdx.y * BM;
    const int j0 = blockIdx.x * BN;
    const int tid  = threadIdx.x;
    const int wid  = tid >> 5;
    const int lane = tid & 31;
    const int g  = lane >> 2;
    const int tg = lane & 3;
    const int wm = (wid & 3) * 32;         // warp M origin (0..96)
    const int wn = (wid >> 2) * 32;        // warp N origin (0 or 32)

    const uint32_t sbar = smem_u32(smem);
    const uint32_t sA = sbar + 1024;
    const uint32_t sB = sA + TILE_A;

    if (tid == 0) MBAR_INIT(sbar, 1);
    __syncthreads();
    if (tid == 0) {
        MBAR_EXPECT_TX(sbar, TILE_A + TILE_B);
        BULK_G2S(sA, (const char*)(g_x0h + ((size_t)b * NP + i0) * HD),
                 TILE_A, sbar);
        BULK_G2S(sB, (const char*)(g_x1h + ((size_t)b * NP + j0) * HD),
                 TILE_B, sbar);
    }

    const size_t bNP = (size_t)b * NP;

    if (tid < BM) s_c[tid] = 0.f;
    else if (tid < BM + BN) s_r[tid - BM] = 0.f;

    const int l7  = lane & 7;
    const int hiA = (lane >> 4) & 1;
    const int hiB = (lane >> 3) & 1;
    const uint32_t baseA = sA + (uint32_t)((wm + (lane & 7) + ((lane >> 3) & 1) * 8) << 8);
    const uint32_t baseB = sB + (uint32_t)((wn + (lane & 7) + ((lane >> 4) & 1) * 8) << 8);

    uint32_t acc[2][4][2];
#pragma unroll
    for (int mi = 0; mi < 2; mi++)
#pragma unroll
        for (int ni = 0; ni < 4; ni++) { acc[mi][ni][0] = 0u; acc[mi][ni][1] = 0u; }

    MBAR_WAIT(sbar, 0);

#pragma unroll
    for (int ks = 0; ks < 8; ks++) {
        const uint32_t offA = (uint32_t)(((2 * ks + hiA) ^ l7) << 4);
        const uint32_t offB = (uint32_t)(((2 * ks + hiB) ^ l7) << 4);
        uint32_t a[2][4], bb[4][2];
#pragma unroll
        for (int mi = 0; mi < 2; mi++)
            ldsm_x4(baseA + mi * 4096 + offA,
                    a[mi][0], a[mi][1], a[mi][2], a[mi][3]);
#pragma unroll
        for (int np = 0; np < 2; np++)
            ldsm_x4(baseB + np * 4096 + offB,
                    bb[np * 2][0], bb[np * 2][1],
                    bb[np * 2 + 1][0], bb[np * 2 + 1][1]);
#pragma unroll
        for (int mi = 0; mi < 2; mi++)
#pragma unroll
            for (int ni = 0; ni < 4; ni++) {
                uint32_t* c = acc[mi][ni];
                asm volatile(
                    "mma.sync.aligned.m16n8k16.row.col.f16.f16.f16.f16 "
                    "{%0,%1}, {%2,%3,%4,%5}, {%6,%7}, {%0,%1};"
                    : "+r"(c[0]), "+r"(c[1])
                    : "r"(a[mi][0]), "r"(a[mi][1]), "r"(a[mi][2]), "r"(a[mi][3]),
                      "r"(bb[ni][0]), "r"(bb[ni][1]));
            }
    }

    // scalars loaded after MMA (cross-CTA overlap hides latency; lower regs)
    float sqi[4];
#pragma unroll
    for (int mi = 0; mi < 2; mi++)
#pragma unroll
        for (int h = 0; h < 2; h++)
            sqi[mi * 2 + h] = g_sq0[bNP + i0 + wm + mi * 16 + h * 8 + g];
    float sqj[8];
#pragma unroll
    for (int ni = 0; ni < 4; ni++)
#pragma unroll
        for (int e = 0; e < 2; e++)
            sqj[ni * 2 + e] = g_sq1[bNP + j0 + wn + ni * 8 + 2 * tg + e];

    float rs[4] = {0.f, 0.f, 0.f, 0.f};
    float cs[8];
#pragma unroll
    for (int i = 0; i < 8; i++) cs[i] = 0.f;

#pragma unroll
    for (int mi = 0; mi < 2; mi++)
#pragma unroll
        for (int ni = 0; ni < 4; ni++)
#pragma unroll
            for (int h = 0; h < 2; h++) {
                float2 cr = __half22float2(*(__half2*)&acc[mi][ni][h]);
#pragma unroll
                for (int e = 0; e < 2; e++) {
                    float cross = (e == 0) ? cr.x : cr.y;
                    float d2 = fmaxf(fmaf(cross, -2.f,
                                          sqi[mi * 2 + h] + sqj[ni * 2 + e]), 0.f);
                    float Aij;
                    if (d2 < 64.f) {
                        Aij = 1.f / (1.f + sqrtf(d2));
                    } else {
                        float u;
                        asm("rsqrt.approx.f32 %0, %1;" : "=f"(u) : "f"(d2));
                        float t = fmaf(-u, 1.f - u, 1.f);
                        Aij = u * fmaf(-u, t, 1.f);
                    }
                    rs[mi * 2 + h] += Aij;
                    cs[ni * 2 + e] += Aij;
                }
            }

#pragma unroll
    for (int i = 0; i < 4; i++) {
        rs[i] += __shfl_xor_sync(0xffffffffu, rs[i], 1);
        rs[i] += __shfl_xor_sync(0xffffffffu, rs[i], 2);
    }
#pragma unroll
    for (int i = 0; i < 8; i++) {
        cs[i] += __shfl_xor_sync(0xffffffffu, cs[i], 4);
        cs[i] += __shfl_xor_sync(0xffffffffu, cs[i], 8);
        cs[i] += __shfl_xor_sync(0xffffffffu, cs[i], 16);
    }
    __syncthreads();
    if (tg == 0) {
#pragma unroll
        for (int mi = 0; mi < 2; mi++)
#pragma unroll
            for (int h = 0; h < 2; h++)
                atomicAdd(&s_c[wm + mi * 16 + h * 8 + g], rs[mi * 2 + h]);
    }
    if (g == 0) {
#pragma unroll
        for (int ni = 0; ni < 4; ni++)
#pragma unroll
            for (int e = 0; e < 2; e++)
                atomicAdd(&s_r[wn + ni * 8 + 2 * tg + e], cs[ni * 2 + e]);
    }
    __syncthreads();

    if (tid < BM) atomicAdd(&g_c[bNP + i0 + tid], s_c[tid]);
    else if (tid < BM + BN) atomicAdd(&g_r[bNP + j0 + (tid - BM)], s_r[tid - BM]);
}

// ---------------------------------------------------------------------------
// Kernel 2b: edge strips (exact fp32 dots), unchanged (verified R10).
// ---------------------------------------------------------------------------
__global__ void edge_kernel(const float* __restrict__ x0,
                            const float* __restrict__ x1) {
    const int mode = blockIdx.y;                 // 0 = E1, 1 = E2
    int gw   = (blockIdx.x * blockDim.x + threadIdx.x) >> 5;
    int lane = threadIdx.x & 31;
    const int nch = (mode == 0) ? 65 : 64;
    int b  = gw / nch;
    int ch = gw - b * nch;
    if (b >= NBATCH) return;

    int t = ch * 32 + lane;
    bool valid = (mode == 0) ? (t < NSB) : (t < NMAIN);
    int tc = valid ? t : 0;

    const float* longRow;
    const float* e0;
    const float* e1;
    if (mode == 0) {
        longRow = x1 + ((size_t)b * NSB + tc) * HD;
        e0 = x0 + ((size_t)b * NSB + 2048) * HD;
        e1 = x0 + ((size_t)b * NSB + 2049) * HD;
    } else {
        longRow = x0 + ((size_t)b * NSB + tc) * HD;
        e0 = x1 + ((size_t)b * NSB + 2048) * HD;
        e1 = x1 + ((size_t)b * NSB + 2049) * HD;
    }

    float d0 = 0.f, d1 = 0.f;
#pragma unroll
    for (int k4 = 0; k4 < HD / 4; k4++) {
        float4 bv = ((const float4*)longRow)[k4];
        float4 a0 = __ldg(&((const float4*)e0)[k4]);
        float4 a1 = __ldg(&((const float4*)e1)[k4]);
        d0 = fmaf(a0.x, bv.x, fmaf(a0.y, bv.y, fmaf(a0.z, bv.z, fmaf(a0.w, bv.w, d0))));
        d1 = fmaf(a1.x, bv.x, fmaf(a1.y, bv.y, fmaf(a1.z, bv.z, fmaf(a1.w, bv.w, d1))));
    }

    const size_t bNP = (size_t)b * NP;
    float sqt, sqe0, sqe1;
    if (mode == 0) {
        sqt  = g_sq1[bNP + tc];
        sqe0 = g_sq0[bNP + 2048];
        sqe1 = g_sq0[bNP + 2049];
    } else {
        sqt  = g_sq0[bNP + tc];
        sqe0 = g_sq1[bNP + 2048];
        sqe1 = g_sq1[bNP + 2049];
    }

    float A0 = 0.f, A1 = 0.f;
    if (valid) {
        float q0 = fmaxf(sqe0 + sqt - 2.f * d0, 0.f);
        float q1 = fmaxf(sqe1 + sqt - 2.f * d1, 0.f);
        A0 = 1.f / (1.f + sqrtf(q0));
        A1 = 1.f / (1.f + sqrtf(q1));
        if (mode == 0) {
            atomicAdd(&g_r[bNP + t], A0 + A1);
        } else {
            atomicAdd(&g_c[bNP + t], A0 + A1);
        }
    }
#pragma unroll
    for (int d = 16; d >= 1; d >>= 1) {
        A0 += __shfl_xor_sync(0xffffffffu, A0, d);
        A1 += __shfl_xor_sync(0xffffffffu, A1, d);
    }
    if (lane == 0) {
        if (mode == 0) {
            atomicAdd(&g_c[bNP + 2048], A0);
            atomicAdd(&g_c[bNP + 2049], A1);
        } else {
            atomicAdd(&g_r[bNP + 2048], A0);
            atomicAdd(&g_r[bNP + 2049], A1);
        }
    }
}

// ---------------------------------------------------------------------------
// Kernel 3: windowed weighted pooling; 2 outputs per thread (row reuse).
// ---------------------------------------------------------------------------
__global__ void window_kernel(const float* __restrict__ x0,
                              const float* __restrict__ x1,
                              float* __restrict__ out) {
    int t = blockIdx.x * blockDim.x + threadIdx.x;
    const int H4 = HD / 4;
    if (t >= NBATCH * (LOUT / 2) * H4) return;
    int h4 = t & 31;
    int lp = (t >> 5) & (LOUT / 2 - 1);
    int b  = t >> 15;
    int l0 = lp * 2;

    const float4* x04 = (const float4*)x0;
    const float4* x14 = (const float4*)x1;
    size_t base = ((size_t)b * NSB + l0) * H4 + h4;

    float rw[4], cw[4];
    float4 v0[4], v1[4];
#pragma unroll
    for (int s = 0; s < 4; s++) {
        rw[s] = g_r[(size_t)b * NP + l0 + s];
        cw[s] = g_c[(size_t)b * NP + l0 + s];
        v0[s] = x04[base + (size_t)s * H4];
        v1[s] = x14[base + (size_t)s * H4];
    }

    float4* o = (float4*)out;
    size_t obase = ((size_t)b * LOUT + l0) * H4 + h4;
    const size_t O1 = (size_t)NBATCH * LOUT * H4;
#pragma unroll
    for (int q = 0; q < 2; q++) {
        float4 a0, a1;
        a0.x = rw[q] * v0[q].x; a0.y = rw[q] * v0[q].y;
        a0.z = rw[q] * v0[q].z; a0.w = rw[q] * v0[q].w;
        a1.x = cw[q] * v1[q].x; a1.y = cw[q] * v1[q].y;
        a1.z = cw[q] * v1[q].z; a1.w = cw[q] * v1[q].w;
#pragma unroll
        for (int s = 1; s < 3; s++) {
            a0.x += rw[q + s] * v0[q + s].x; a0.y += rw[q + s] * v0[q + s].y;
            a0.z += rw[q + s] * v0[q + s].z; a0.w += rw[q + s] * v0[q + s].w;
            a1.x += cw[q + s] * v1[q + s].x; a1.y += cw[q + s] * v1[q + s].y;
            a1.z += cw[q + s] * v1[q + s].z; a1.w += cw[q + s] * v1[q + s].w;
        }
        o[obase + (size_t)q * H4] = a0;
        o[O1 + obase + (size_t)q * H4] = a1;
    }
}

// ---------------------------------------------------------------------------
extern "C" void kernel_launch(void* const* d_in, const int* in_sizes, int n_in,
                              void* d_out, int out_size) {
    const float* x0 = (const float*)d_in[0];
    const float* x1 = (const float*)d_in[1];
    float* out = (float*)d_out;

    cudaFuncSetAttribute(dist_kernel,
                         cudaFuncAttributeMaxDynamicSharedMemorySize, SM_TOTAL);

    prep_kernel<<<(NBATCH * NP * 32 + 255) / 256, 256>>>(x0, x1);

    dim3 grid(NMAIN / BN, NMAIN / BM, NBATCH);   // 32 x 16 x 32
    dist_kernel<<<grid, 256, SM_TOTAL>>>();

    dim3 egrid((NBATCH * 65 * 32 + 255) / 256, 2, 1);
    edge_kernel<<<egrid, 256>>>(x0, x1);

    window_kernel<<<(NBATCH * (LOUT / 2) * (HD / 4) + 255) / 256, 256>>>(x0, x1, out);
}